// round 16
// baseline (speedup 1.0000x reference)
#include <cuda_runtime.h>
#include <math.h>

#define BB 4
#define NN 32
#define DD 128
#define HH 8
#define NCC 27
#define DFF 512
#define LL (NCC*NN)        // 864
#define NR (BB*NN)         // 128 token rows
#define GRID NR
#define TPB 1024

// ---------------- scratch (static device globals; no allocation) -------------
__device__ float g_mxb[NR], g_ssxb[NR];
__device__ float g_XW[NR*3];
__device__ __align__(16) float g_Xk[NR*DD], g_Xv[NR*DD];
__device__ __align__(16) float g_Mv[3*DD];
__device__ float g_Mk[3*DD];
__device__ float g_uq[DD], g_uk[DD], g_uv[DD];
__device__ float g_cq[DD], g_ck[DD], g_cv[DD];
__device__ float g_G[9], g_rs[3];
__device__ unsigned g_tick;            // monotonic barrier ticket (never reset)

__inline__ __device__ float warpSum(float v){
    #pragma unroll
    for (int o = 16; o; o >>= 1) v += __shfl_down_sync(0xffffffffu, v, o);
    return v;
}

__global__ void __launch_bounds__(TPB, 1)
k_fused(const float* __restrict__ x, const int* __restrict__ mask,
        const float* __restrict__ coords,
        const float* __restrict__ Wp, const float* __restrict__ bp,
        const float* __restrict__ Wq, const float* __restrict__ bq,
        const float* __restrict__ Wk, const float* __restrict__ bk,
        const float* __restrict__ Wv, const float* __restrict__ bv,
        const float* __restrict__ Wo, const float* __restrict__ bo,
        const float* __restrict__ g1, const float* __restrict__ b1,
        const float* __restrict__ g2, const float* __restrict__ b2,
        const float* __restrict__ W1, const float* __restrict__ bf1,
        const float* __restrict__ W2, const float* __restrict__ bf2,
        float* __restrict__ out)
{
    // big overlay buffer (= 8*864 floats, 27.6 KB), phase-specific layouts
    __shared__ __align__(16) float s_buf[HH*LL];
    __shared__ float s_rstd[LL];
    __shared__ float s_dc0[LL], s_dc1[LL], s_dc2[LL];   // coord deltas (phase-1 prefetch)
    __shared__ float s_xb[128], s_Xq[128], s_yrow[128], s_hn2[128], s_atts[128];
    __shared__ float s_QXk[HH][32];
    __shared__ float s_qMk[HH][4], s_quk[HH], s_qck[HH];
    __shared__ float s_A[HH][32], s_B[HH][4], s_G8[HH];
    __shared__ float s_Ap[4][HH][32], s_Bp[4][HH][4], s_Gp4[4][HH];
    __shared__ float s_sm4[4][HH][2];
    __shared__ float s_mxb[32], s_ssxb[32], s_XW[32][3];
    __shared__ float rsm[4][2];
    __shared__ int   mk[32];

    int bid = blockIdx.x, tid = threadIdx.x;
    int b = bid >> 5, i = bid & 31;
    int lane = tid & 31;
    int w = tid >> 5;
    const float* cb = coords + b*LL*3;

    // ===================== PHASE 1: precomputes ==============================
    {
        float* part  = s_buf;          // 3*8*128 = 3072
        float* paux  = s_buf + 3072;   // 8*128 = 1024
        float* s_xbg = s_buf + 4096;   // 128
        float* s_aux = s_buf + 4224;   // 128

        if (tid < 128){
            float xv = x[bid*DD + tid] + bp[tid];
            s_xb[tid]  = xv;
            s_xbg[tid] = xv * g1[tid];
            float p0 = xv * Wp[tid], p1 = xv * Wp[DD+tid], p2 = xv * Wp[2*DD+tid];
            float s = warpSum(xv), ss = warpSum(xv*xv);
            p0 = warpSum(p0); p1 = warpSum(p1); p2 = warpSum(p2);
            if (lane == 0){
                rsm[w][0] = s; rsm[w][1] = ss;
                s_XW[w][0] = p0; s_XW[w][1] = p1; s_XW[w][2] = p2;  // temp reuse
            }
        } else if (bid < 12 && tid >= 896){
            int t = tid - 896;
            int unit = bid;
            if (unit < 6)      s_aux[t] = Wp[(unit%3)*DD + t] * g1[t];
            else if (unit < 9) s_aux[t] = g1[t];
            else               s_aux[t] = b1[t];
        }
        __syncthreads();

        if (tid == 0){
            g_mxb[bid]  = (rsm[0][0]+rsm[1][0]+rsm[2][0]+rsm[3][0]) * (1.0f/128.0f);
            g_ssxb[bid] =  rsm[0][1]+rsm[1][1]+rsm[2][1]+rsm[3][1];
        } else if (tid < 4){
            g_XW[bid*3 + (tid-1)] = s_XW[0][tid-1]+s_XW[1][tid-1]+s_XW[2][tid-1]+s_XW[3][tid-1];
        }

        if (tid < 768){
            // row GEMMs: 3 matrices x 32 col-quads x 8 k-octants, float4, coalesced
            int m = tid >> 8, r = tid & 255;
            int cg = r & 31, ko = r >> 5;
            int k0 = ko*16, j4 = cg*4;
            const float* W = (m==0) ? Wq : ((m==1) ? Wk : Wv);
            const float* Wb = W + k0*DD + j4;
            float a0=0.f, a1=0.f, a2=0.f, a3=0.f;
            #pragma unroll
            for (int kk = 0; kk < 16; kk++){
                float a = s_xbg[k0+kk];
                float4 wv = *(const float4*)&Wb[kk*DD];
                a0 = fmaf(a, wv.x, a0); a1 = fmaf(a, wv.y, a1);
                a2 = fmaf(a, wv.z, a2); a3 = fmaf(a, wv.w, a3);
            }
            float4 o; o.x=a0; o.y=a1; o.z=a2; o.w=a3;
            *(float4*)&part[m*1024 + ko*128 + j4] = o;
        } else {
            if (bid < 12){
                int t = tid - 768;
                int cg = t & 31, ko = t >> 5;
                int k0 = ko*16, j4 = cg*4;
                int unit = bid;
                const float* W;
                if (unit < 3)       W = Wk;
                else if (unit < 6)  W = Wv;
                else if (unit == 6 || unit == 9)  W = Wq;
                else if (unit == 7 || unit == 10) W = Wk;
                else                W = Wv;
                const float* Wb = W + k0*DD + j4;
                float a0=0.f, a1=0.f, a2=0.f, a3=0.f;
                #pragma unroll
                for (int kk = 0; kk < 16; kk++){
                    float a = s_aux[k0+kk];
                    float4 wv = *(const float4*)&Wb[kk*DD];
                    a0 = fmaf(a, wv.x, a0); a1 = fmaf(a, wv.y, a1);
                    a2 = fmaf(a, wv.z, a2); a3 = fmaf(a, wv.w, a3);
                }
                float4 o; o.x=a0; o.y=a1; o.z=a2; o.w=a3;
                *(float4*)&paux[ko*128 + j4] = o;
            } else if (bid == 12){
                // G = Wp Wp^T (9), rs (3)
                int ww = (tid - 768) >> 5;
                for (int o = ww; o < 12; o += 8){
                    float acc = 0.0f;
                    if (o < 9){
                        int a = o/3, c = o%3;
                        #pragma unroll
                        for (int q4 = 0; q4 < 4; q4++){
                            int k = lane + q4*32;
                            acc = fmaf(Wp[a*DD+k], Wp[c*DD+k], acc);
                        }
                        acc = warpSum(acc);
                        if (lane == 0) g_G[o] = acc;
                    } else {
                        int a = o - 9;
                        #pragma unroll
                        for (int q4 = 0; q4 < 4; q4++) acc += Wp[a*DD + lane + q4*32];
                        acc = warpSum(acc);
                        if (lane == 0) g_rs[a] = acc;
                    }
                }
            }
            // coord-delta prefetch: overlapped with row-GEMM latency
            for (int l = tid - 768; l < LL; l += 256){
                int c = l >> 5;
                int lb = l*3, ib = (c*32 + i)*3;
                s_dc0[l] = cb[lb]   - cb[ib];
                s_dc1[l] = cb[lb+1] - cb[ib+1];
                s_dc2[l] = cb[lb+2] - cb[ib+2];
            }
        }
        __syncthreads();

        if (tid < 384){
            int m = tid >> 7, j = tid & 127;
            const float* pm = part + m*1024;
            float v = pm[j] + pm[128+j] + pm[256+j] + pm[384+j]
                    + pm[512+j] + pm[640+j] + pm[768+j] + pm[896+j];
            if      (m == 0) s_Xq[j] = v;
            else if (m == 1) g_Xk[bid*DD + j] = v;
            else             g_Xv[bid*DD + j] = v;
        } else if (bid < 12 && tid >= 384 && tid < 512){
            int j = tid - 384;
            int unit = bid;
            float* O; const float* bias = 0;
            if (unit < 3)      O = g_Mk + unit*DD;
            else if (unit < 6) O = g_Mv + (unit-3)*DD;
            else if (unit == 6) O = g_uq;
            else if (unit == 7) O = g_uk;
            else if (unit == 8) O = g_uv;
            else if (unit == 9){ O = g_cq; bias = bq; }
            else if (unit ==10){ O = g_ck; bias = bk; }
            else               { O = g_cv; bias = bv; }
            float v = paux[j] + paux[128+j] + paux[256+j] + paux[384+j]
                    + paux[512+j] + paux[640+j] + paux[768+j] + paux[896+j];
            O[j] = v + (bias ? bias[j] : 0.0f);
        }
    }

    // ===================== GLOBAL BARRIER (ticket + backoff spin) =============
    __syncthreads();
    if (tid == 0){
        __threadfence();
        unsigned my = atomicAdd(&g_tick, 1u);
        unsigned target = (my / GRID + 1u) * GRID;
        volatile unsigned* vt = &g_tick;
        while (*vt < target) { __nanosleep(64); }
        __threadfence();
    }
    __syncthreads();

    // ===================== PHASE 2: attention (factored) =====================
    {
        float* s_q = s_buf;   // temp overlay until scores are written

        if (tid < 32){
            mk[tid]     = mask[b*32 + tid];
            s_mxb[tid]  = g_mxb[b*32 + tid];
            s_ssxb[tid] = g_ssxb[b*32 + tid];
        }
        if (tid >= 416 && tid < 512){
            int t = tid - 416;
            s_XW[t/3][t%3] = g_XW[b*96 + t];
        }
        if (tid >= 128 && tid < 256){
            int d = tid - 128;
            float mu_i = g_mxb[bid];
            float rstd_i = rsqrtf(g_ssxb[bid]*(1.0f/128.0f) - mu_i*mu_i + 1e-5f);
            s_q[d] = rstd_i*s_Xq[d] - rstd_i*mu_i*g_uq[d] + g_cq[d];
        }
        __syncthreads();

        // q-side precomputes, 1/sqrt(DK)=0.25 folded in here
        if (tid < 256){
            int h = tid >> 5, n = tid & 31;
            const float4* q4 = (const float4*)&s_q[h*16];
            const float4* k4 = (const float4*)&g_Xk[(b*32+n)*DD + h*16];
            float acc = 0.0f;
            #pragma unroll
            for (int j = 0; j < 4; j++){
                float4 qq = q4[j], kk = k4[j];
                acc = fmaf(qq.x, kk.x, fmaf(qq.y, kk.y,
                      fmaf(qq.z, kk.z, fmaf(qq.w, kk.w, acc))));
            }
            s_QXk[h][n] = acc * 0.25f;
        } else if (tid < 280){
            int t = tid - 256;
            int h = t/3, a = t%3;
            float acc = 0.0f;
            #pragma unroll
            for (int j = 0; j < 16; j++) acc = fmaf(s_q[h*16+j], g_Mk[a*DD + h*16 + j], acc);
            s_qMk[h][a] = acc * 0.25f;
        } else if (tid < 288){
            int h = tid - 280;
            float acc = 0.0f;
            #pragma unroll
            for (int j = 0; j < 16; j++) acc = fmaf(s_q[h*16+j], g_uk[h*16+j], acc);
            s_quk[h] = acc * 0.25f;
        } else if (tid < 296){
            int h = tid - 288;
            float acc = 0.0f;
            #pragma unroll
            for (int j = 0; j < 16; j++) acc = fmaf(s_q[h*16+j], g_ck[h*16+j], acc);
            s_qck[h] = acc * 0.25f;
        }
        __syncthreads();
    }

    // scores + LN stats: one key per thread (deltas already in smem)
    if (tid < LL){
        int l = tid;
        int n = l & 31;
        float d0 = s_dc0[l], d1 = s_dc1[l], d2 = s_dc2[l];
        float mu = s_mxb[n] + (d0*g_rs[0] + d1*g_rs[1] + d2*g_rs[2]) * (1.0f/128.0f);
        float ss = s_ssxb[n]
                 + 2.0f*(d0*s_XW[n][0] + d1*s_XW[n][1] + d2*s_XW[n][2])
                 + d0*(g_G[0]*d0 + g_G[1]*d1 + g_G[2]*d2)
                 + d1*(g_G[3]*d0 + g_G[4]*d1 + g_G[5]*d2)
                 + d2*(g_G[6]*d0 + g_G[7]*d1 + g_G[8]*d2);
        float var = ss*(1.0f/128.0f) - mu*mu;
        float rstd = rsqrtf(var + 1e-5f);
        s_rstd[l] = rstd;
        float rm = rstd*mu;
        bool msk = (mk[n] == 0);
        #pragma unroll
        for (int h = 0; h < 8; h++){
            float s = rstd*(s_QXk[h][n] + d0*s_qMk[h][0] + d1*s_qMk[h][1] + d2*s_qMk[h][2])
                    - rm*s_quk[h] + s_qck[h];
            s_buf[h*LL + l] = msk ? -1e9f : s;
        }
    }
    __syncthreads();

    // softmax: 4 warps per head; warp q owns keys with c = q (mod 4)
    {
        int h = w & 7, q = w >> 3;
        int start = q*32 + lane;
        float* sch = s_buf + h*LL;
        float m = -3.4e38f;
        for (int l = start; l < LL; l += 128) m = fmaxf(m, sch[l]);
        #pragma unroll
        for (int o = 16; o; o >>= 1) m = fmaxf(m, __shfl_xor_sync(0xffffffffu, m, o));
        float sum = 0.0f;
        for (int l = start; l < LL; l += 128){
            float e = __expf(sch[l] - m);
            sch[l] = e;
            sum += e;
        }
        #pragma unroll
        for (int o = 16; o; o >>= 1) sum += __shfl_xor_sync(0xffffffffu, sum, o);
        if (lane == 0){ s_sm4[q][h][0] = m; s_sm4[q][h][1] = sum; }
    }
    __syncthreads();

    // V aggregates: warp (q,h) covers c = q (mod 4) — SAME keys its softmax
    // quarter normalized, so ONE constant merge-scale per warp, factored out.
    // Gp derived analytically: mu = mxb[n] + dc.rs/128 =>
    //   sum(-wr*mu) = -mxb[n]*A - (rs.B)/128 per lane.
    {
        int n = lane;
        int h = w & 7, q = w >> 3;
        float m0 = s_sm4[0][h][0], m1 = s_sm4[1][h][0];
        float m2 = s_sm4[2][h][0], m3 = s_sm4[3][h][0];
        float M = fmaxf(fmaxf(m0, m1), fmaxf(m2, m3));
        float e0 = __expf(m0-M), e1 = __expf(m1-M), e2 = __expf(m2-M), e3 = __expf(m3-M);
        float Sinv = 1.0f/(s_sm4[0][h][1]*e0 + s_sm4[1][h][1]*e1
                         + s_sm4[2][h][1]*e2 + s_sm4[3][h][1]*e3);
        float scl = ((q==0) ? e0 : ((q==1) ? e1 : ((q==2) ? e2 : e3))) * Sinv;

        const float* sch = s_buf + h*LL;
        float A = 0.f, B0 = 0.f, B1 = 0.f, B2 = 0.f;
        #pragma unroll 1
        for (int c = q; c < NCC; c += 4){
            int l = c*32 + n;
            float wr = sch[l] * s_rstd[l];
            A += wr;
            B0 = fmaf(wr, s_dc0[l], B0);
            B1 = fmaf(wr, s_dc1[l], B1);
            B2 = fmaf(wr, s_dc2[l], B2);
        }
        float Gp = -s_mxb[n]*A
                 - (B0*g_rs[0] + B1*g_rs[1] + B2*g_rs[2]) * (1.0f/128.0f);
        A *= scl; B0 *= scl; B1 *= scl; B2 *= scl; Gp *= scl;
        s_Ap[q][h][n] = A;
        B0 = warpSum(B0); B1 = warpSum(B1); B2 = warpSum(B2); Gp = warpSum(Gp);
        if (n == 0){
            s_Bp[q][h][0]=B0; s_Bp[q][h][1]=B1; s_Bp[q][h][2]=B2; s_Gp4[q][h]=Gp;
        }
    }
    __syncthreads();
    if (tid < 256){
        int h = tid >> 5, n = tid & 31;
        s_A[h][n] = s_Ap[0][h][n] + s_Ap[1][h][n] + s_Ap[2][h][n] + s_Ap[3][h][n];
    } else if (tid < 280){
        int t = tid - 256;
        int h = t/3, a = t%3;
        s_B[h][a] = s_Bp[0][h][a] + s_Bp[1][h][a] + s_Bp[2][h][a] + s_Bp[3][h][a];
    } else if (tid < 288){
        int h = tid - 280;
        s_G8[h] = s_Gp4[0][h] + s_Gp4[1][h] + s_Gp4[2][h] + s_Gp4[3][h];
    }
    __syncthreads();

    // atts: n-split 8 (4-iter chains), coalesced Xv reads
    {
        float* pa = s_buf;             // 1024 partials
        {
            int d = tid & 127, nh = tid >> 7;
            int h = d >> 4;
            float acc;
            if (nh == 0){
                acc = g_cv[d] + s_G8[h]*g_uv[d]
                    + s_B[h][0]*g_Mv[d] + s_B[h][1]*g_Mv[DD+d] + s_B[h][2]*g_Mv[2*DD+d];
            } else acc = 0.0f;
            const float* Xvb = g_Xv + b*32*DD;
            int n0 = nh*4;
            #pragma unroll
            for (int n = 0; n < 4; n++) acc = fmaf(s_A[h][n0+n], Xvb[(n0+n)*DD + d], acc);
            pa[nh*128 + d] = acc;
        }
        __syncthreads();
        if (tid < 128)
            s_atts[tid] = pa[tid] + pa[128+tid] + pa[256+tid] + pa[384+tid]
                        + pa[512+tid] + pa[640+tid] + pa[768+tid] + pa[896+tid];
        __syncthreads();

        // Wo: 32 col-quads x 32 k-splits (4 k each), float4, coalesced
        float* red = s_buf;            // 4096 partials
        {
            int cg = tid & 31, ks = tid >> 5;
            int k0 = ks*4, j4 = cg*4;
            const float* Wb = Wo + k0*DD + j4;
            float a0=0.f, a1=0.f, a2=0.f, a3=0.f;
            #pragma unroll
            for (int kk = 0; kk < 4; kk++){
                float a = s_atts[k0+kk];
                float4 wv = *(const float4*)&Wb[kk*DD];
                a0 = fmaf(a, wv.x, a0); a1 = fmaf(a, wv.y, a1);
                a2 = fmaf(a, wv.z, a2); a3 = fmaf(a, wv.w, a3);
            }
            float4 o; o.x=a0; o.y=a1; o.z=a2; o.w=a3;
            *(float4*)&red[ks*128 + j4] = o;
        }
        __syncthreads();

        // y = xb + bo + sum(32 partials); warp stats; then warp0 LN2+hn2
        if (tid < 128){
            float y = s_xb[tid] + bo[tid];
            #pragma unroll
            for (int t = 0; t < 32; t++) y += red[t*128 + tid];
            s_yrow[tid] = y;
            float s = warpSum(y), s2 = warpSum(y*y);
            if (lane == 0){ rsm[w][0] = s; rsm[w][1] = s2; }
        }
        __syncthreads();
        if (tid < 32){
            float s  = rsm[0][0]+rsm[1][0]+rsm[2][0]+rsm[3][0];
            float s2 = rsm[0][1]+rsm[1][1]+rsm[2][1]+rsm[3][1];
            float m = s * (1.0f/128.0f);
            float rstd = rsqrtf(s2*(1.0f/128.0f) - m*m + 1e-5f);
            #pragma unroll
            for (int r = 0; r < 4; r++){
                int d = r*32 + lane;
                s_hn2[d] = (s_yrow[d] - m)*rstd*g2[d] + b2[d];
            }
        }
        __syncthreads();
    }

    // ===================== PHASE 3: FFN (float4, coalesced) ===================
    {
        float* zp = s_buf;             // 8*512 = 4096 partials
        float* zs = s_buf + 4096;      // 512

        // stage 1: 128 col-quads x 8 k-octants, full unroll
        {
            int cg = tid & 127, ko = tid >> 7;
            int k0 = ko*16, j4 = cg*4;
            const float* Wb = W1 + k0*DFF + j4;
            float a0=0.f, a1=0.f, a2=0.f, a3=0.f;
            #pragma unroll
            for (int kk = 0; kk < 16; kk++){
                float a = s_hn2[k0+kk];
                float4 wv = *(const float4*)&Wb[kk*DFF];
                a0 = fmaf(a, wv.x, a0); a1 = fmaf(a, wv.y, a1);
                a2 = fmaf(a, wv.z, a2); a3 = fmaf(a, wv.w, a3);
            }
            float4 o; o.x=a0; o.y=a1; o.z=a2; o.w=a3;
            *(float4*)&zp[ko*512 + j4] = o;
        }
        __syncthreads();
        if (tid < 512){
            float v = zp[tid] + zp[512+tid] + zp[1024+tid] + zp[1536+tid]
                    + zp[2048+tid] + zp[2560+tid] + zp[3072+tid] + zp[3584+tid];
            zs[tid] = fmaxf(v + bf1[tid], 0.0f);
        }
        __syncthreads();

        // stage 2: 32 col-quads x 32 k-splits (16 k each), full unroll
        float* red = s_buf;            // 4096 (zp region reused; zs disjoint)
        {
            int cg = tid & 31, ks = tid >> 5;
            int k0 = ks*16, j4 = cg*4;
            const float* Wb = W2 + k0*DD + j4;
            float a0=0.f, a1=0.f, a2=0.f, a3=0.f;
            #pragma unroll
            for (int kk = 0; kk < 16; kk++){
                float a = zs[k0+kk];
                float4 wv = *(const float4*)&Wb[kk*DD];
                a0 = fmaf(a, wv.x, a0); a1 = fmaf(a, wv.y, a1);
                a2 = fmaf(a, wv.z, a2); a3 = fmaf(a, wv.w, a3);
            }
            float4 o; o.x=a0; o.y=a1; o.z=a2; o.w=a3;
            *(float4*)&red[ks*128 + j4] = o;
        }
        __syncthreads();

        // final: 128 threads sum all 32 partials straight into out
        if (tid < 128){
            float v = s_yrow[tid] + bf2[tid];
            #pragma unroll
            for (int t = 0; t < 32; t++) v += red[t*128 + tid];
            out[bid*DD + tid] = v;
        }
    }
}

// ---------------- launch ------------------------------------------------------
extern "C" void kernel_launch(void* const* d_in, const int* in_sizes, int n_in,
                              void* d_out, int out_size)
{
    const float* x      = (const float*)d_in[0];
    const int*   mask   = (const int*)  d_in[1];
    const float* coords = (const float*)d_in[2];
    const float* Wp = (const float*)d_in[3],  *bp  = (const float*)d_in[4];
    const float* Wq = (const float*)d_in[5],  *bq  = (const float*)d_in[6];
    const float* Wk = (const float*)d_in[7],  *bk  = (const float*)d_in[8];
    const float* Wv = (const float*)d_in[9],  *bv  = (const float*)d_in[10];
    const float* Wo = (const float*)d_in[11], *bo  = (const float*)d_in[12];
    const float* g1 = (const float*)d_in[13], *b1  = (const float*)d_in[14];
    const float* g2 = (const float*)d_in[15], *b2  = (const float*)d_in[16];
    const float* W1 = (const float*)d_in[17], *bf1 = (const float*)d_in[18];
    const float* W2 = (const float*)d_in[19], *bf2 = (const float*)d_in[20];
    float* out = (float*)d_out;

    k_fused<<<GRID, TPB>>>(x, mask, coords, Wp, bp, Wq, bq, Wk, bk, Wv, bv,
                           Wo, bo, g1, b1, g2, b2, W1, bf1, W2, bf2, out);
}

// round 17
// speedup vs baseline: 1.0015x; 1.0015x over previous
#include <cuda_runtime.h>
#include <math.h>

#define BB 4
#define NN 32
#define DD 128
#define HH 8
#define NCC 27
#define DFF 512
#define LL (NCC*NN)        // 864
#define NR (BB*NN)         // 128 token rows
#define GRID NR
#define TPB 1024
#define QSCALE (0.25f * 1.44269504088896340736f)   // 1/sqrt(DK) * log2(e)

// ---------------- scratch (static device globals; no allocation) -------------
__device__ float g_mxb[NR], g_ssxb[NR];
__device__ float g_XW[NR*3];
__device__ __align__(16) float g_Xk[NR*DD], g_Xv[NR*DD];
__device__ __align__(16) float g_Mv[3*DD];
__device__ float g_Mk[3*DD];
__device__ float g_uq[DD], g_uk[DD], g_uv[DD];
__device__ float g_cq[DD], g_ck[DD], g_cv[DD];
__device__ float g_G[9], g_rs[3];
__device__ unsigned g_tick;            // monotonic barrier ticket (never reset)

__inline__ __device__ float warpSum(float v){
    #pragma unroll
    for (int o = 16; o; o >>= 1) v += __shfl_down_sync(0xffffffffu, v, o);
    return v;
}

__global__ void __launch_bounds__(TPB, 1)
k_fused(const float* __restrict__ x, const int* __restrict__ mask,
        const float* __restrict__ coords,
        const float* __restrict__ Wp, const float* __restrict__ bp,
        const float* __restrict__ Wq, const float* __restrict__ bq,
        const float* __restrict__ Wk, const float* __restrict__ bk,
        const float* __restrict__ Wv, const float* __restrict__ bv,
        const float* __restrict__ Wo, const float* __restrict__ bo,
        const float* __restrict__ g1, const float* __restrict__ b1,
        const float* __restrict__ g2, const float* __restrict__ b2,
        const float* __restrict__ W1, const float* __restrict__ bf1,
        const float* __restrict__ W2, const float* __restrict__ bf2,
        float* __restrict__ out)
{
    // big overlay buffer (= 8*864 floats, 27.6 KB), phase-specific layouts
    __shared__ __align__(16) float s_buf[HH*LL];
    __shared__ float s_rstd[LL];
    __shared__ float s_dc0[LL], s_dc1[LL], s_dc2[LL];   // coord deltas (phase-1 prefetch)
    __shared__ float s_xb[128], s_Xq[128], s_yrow[128], s_hn2[128], s_atts[128];
    __shared__ float s_QXk[HH][32];
    __shared__ float s_qMk[HH][4], s_quk[HH], s_qck[HH];
    __shared__ float s_A[HH][32], s_B[HH][4], s_G8[HH];
    __shared__ float s_Ap[4][HH][32], s_Bp[4][HH][4], s_Gp4[4][HH];
    __shared__ float s_sm4[4][HH][2];
    __shared__ float s_mxb[32], s_ssxb[32], s_XW[32][3];
    __shared__ float rsm[4][2];
    __shared__ int   mk[32];

    int bid = blockIdx.x, tid = threadIdx.x;
    int b = bid >> 5, i = bid & 31;
    int lane = tid & 31;
    int w = tid >> 5;
    const float* cb = coords + b*LL*3;

    // ===================== PHASE 1: precomputes ==============================
    {
        float* part  = s_buf;          // 3*8*128 = 3072
        float* paux  = s_buf + 3072;   // 8*128 = 1024
        float* s_xbg = s_buf + 4096;   // 128
        float* s_aux = s_buf + 4224;   // 128

        if (tid < 128){
            float xv = x[bid*DD + tid] + bp[tid];
            s_xb[tid]  = xv;
            s_xbg[tid] = xv * g1[tid];
            float p0 = xv * Wp[tid], p1 = xv * Wp[DD+tid], p2 = xv * Wp[2*DD+tid];
            float s = warpSum(xv), ss = warpSum(xv*xv);
            p0 = warpSum(p0); p1 = warpSum(p1); p2 = warpSum(p2);
            if (lane == 0){
                rsm[w][0] = s; rsm[w][1] = ss;
                s_XW[w][0] = p0; s_XW[w][1] = p1; s_XW[w][2] = p2;  // temp reuse
            }
        } else if (bid < 12 && tid >= 896){
            int t = tid - 896;
            int unit = bid;
            if (unit < 6)      s_aux[t] = Wp[(unit%3)*DD + t] * g1[t];
            else if (unit < 9) s_aux[t] = g1[t];
            else               s_aux[t] = b1[t];
        }
        __syncthreads();

        if (tid == 0){
            g_mxb[bid]  = (rsm[0][0]+rsm[1][0]+rsm[2][0]+rsm[3][0]) * (1.0f/128.0f);
            g_ssxb[bid] =  rsm[0][1]+rsm[1][1]+rsm[2][1]+rsm[3][1];
        } else if (tid < 4){
            g_XW[bid*3 + (tid-1)] = s_XW[0][tid-1]+s_XW[1][tid-1]+s_XW[2][tid-1]+s_XW[3][tid-1];
        }

        if (tid < 768){
            // row GEMMs: 3 matrices x 32 col-quads x 8 k-octants, float4, coalesced
            int m = tid >> 8, r = tid & 255;
            int cg = r & 31, ko = r >> 5;
            int k0 = ko*16, j4 = cg*4;
            const float* W = (m==0) ? Wq : ((m==1) ? Wk : Wv);
            const float* Wb = W + k0*DD + j4;
            float a0=0.f, a1=0.f, a2=0.f, a3=0.f;
            #pragma unroll
            for (int kk = 0; kk < 16; kk++){
                float a = s_xbg[k0+kk];
                float4 wv = *(const float4*)&Wb[kk*DD];
                a0 = fmaf(a, wv.x, a0); a1 = fmaf(a, wv.y, a1);
                a2 = fmaf(a, wv.z, a2); a3 = fmaf(a, wv.w, a3);
            }
            float4 o; o.x=a0; o.y=a1; o.z=a2; o.w=a3;
            *(float4*)&part[m*1024 + ko*128 + j4] = o;
        } else {
            if (bid < 12){
                int t = tid - 768;
                int cg = t & 31, ko = t >> 5;
                int k0 = ko*16, j4 = cg*4;
                int unit = bid;
                const float* W;
                if (unit < 3)       W = Wk;
                else if (unit < 6)  W = Wv;
                else if (unit == 6 || unit == 9)  W = Wq;
                else if (unit == 7 || unit == 10) W = Wk;
                else                W = Wv;
                const float* Wb = W + k0*DD + j4;
                float a0=0.f, a1=0.f, a2=0.f, a3=0.f;
                #pragma unroll
                for (int kk = 0; kk < 16; kk++){
                    float a = s_aux[k0+kk];
                    float4 wv = *(const float4*)&Wb[kk*DD];
                    a0 = fmaf(a, wv.x, a0); a1 = fmaf(a, wv.y, a1);
                    a2 = fmaf(a, wv.z, a2); a3 = fmaf(a, wv.w, a3);
                }
                float4 o; o.x=a0; o.y=a1; o.z=a2; o.w=a3;
                *(float4*)&paux[ko*128 + j4] = o;
            } else if (bid == 12){
                // G = Wp Wp^T (9), rs (3)
                int ww = (tid - 768) >> 5;
                for (int o = ww; o < 12; o += 8){
                    float acc = 0.0f;
                    if (o < 9){
                        int a = o/3, c = o%3;
                        #pragma unroll
                        for (int q4 = 0; q4 < 4; q4++){
                            int k = lane + q4*32;
                            acc = fmaf(Wp[a*DD+k], Wp[c*DD+k], acc);
                        }
                        acc = warpSum(acc);
                        if (lane == 0) g_G[o] = acc;
                    } else {
                        int a = o - 9;
                        #pragma unroll
                        for (int q4 = 0; q4 < 4; q4++) acc += Wp[a*DD + lane + q4*32];
                        acc = warpSum(acc);
                        if (lane == 0) g_rs[a] = acc;
                    }
                }
            }
            // coord-delta prefetch: overlapped with row-GEMM latency
            for (int l = tid - 768; l < LL; l += 256){
                int c = l >> 5;
                int lb = l*3, ib = (c*32 + i)*3;
                s_dc0[l] = cb[lb]   - cb[ib];
                s_dc1[l] = cb[lb+1] - cb[ib+1];
                s_dc2[l] = cb[lb+2] - cb[ib+2];
            }
        }
        __syncthreads();

        if (tid < 384){
            int m = tid >> 7, j = tid & 127;
            const float* pm = part + m*1024;
            float v = pm[j] + pm[128+j] + pm[256+j] + pm[384+j]
                    + pm[512+j] + pm[640+j] + pm[768+j] + pm[896+j];
            if      (m == 0) s_Xq[j] = v;
            else if (m == 1) g_Xk[bid*DD + j] = v;
            else             g_Xv[bid*DD + j] = v;
        } else if (bid < 12 && tid >= 384 && tid < 512){
            int j = tid - 384;
            int unit = bid;
            float* O; const float* bias = 0;
            if (unit < 3)      O = g_Mk + unit*DD;
            else if (unit < 6) O = g_Mv + (unit-3)*DD;
            else if (unit == 6) O = g_uq;
            else if (unit == 7) O = g_uk;
            else if (unit == 8) O = g_uv;
            else if (unit == 9){ O = g_cq; bias = bq; }
            else if (unit ==10){ O = g_ck; bias = bk; }
            else               { O = g_cv; bias = bv; }
            float v = paux[j] + paux[128+j] + paux[256+j] + paux[384+j]
                    + paux[512+j] + paux[640+j] + paux[768+j] + paux[896+j];
            O[j] = v + (bias ? bias[j] : 0.0f);
        }
    }

    // ===================== GLOBAL BARRIER (ticket + backoff spin) =============
    __syncthreads();
    if (tid == 0){
        __threadfence();
        unsigned my = atomicAdd(&g_tick, 1u);
        unsigned target = (my / GRID + 1u) * GRID;
        volatile unsigned* vt = &g_tick;
        while (*vt < target) { __nanosleep(64); }
        __threadfence();
    }
    __syncthreads();

    // ===================== PHASE 2: attention (factored, exp2 domain) ========
    {
        float* s_q = s_buf;   // temp overlay until scores are written

        if (tid < 32){
            mk[tid]     = mask[b*32 + tid];
            s_mxb[tid]  = g_mxb[b*32 + tid];
            s_ssxb[tid] = g_ssxb[b*32 + tid];
        }
        if (tid >= 416 && tid < 512){
            int t = tid - 416;
            s_XW[t/3][t%3] = g_XW[b*96 + t];
        }
        if (tid >= 128 && tid < 256){
            int d = tid - 128;
            float mu_i = g_mxb[bid];
            float rstd_i = rsqrtf(g_ssxb[bid]*(1.0f/128.0f) - mu_i*mu_i + 1e-5f);
            s_q[d] = rstd_i*s_Xq[d] - rstd_i*mu_i*g_uq[d] + g_cq[d];
        }
        __syncthreads();

        // q-side precomputes; 0.25*log2(e) folded in (exp2 softmax domain)
        if (tid < 256){
            int h = tid >> 5, n = tid & 31;
            const float4* q4 = (const float4*)&s_q[h*16];
            const float4* k4 = (const float4*)&g_Xk[(b*32+n)*DD + h*16];
            float acc = 0.0f;
            #pragma unroll
            for (int j = 0; j < 4; j++){
                float4 qq = q4[j], kk = k4[j];
                acc = fmaf(qq.x, kk.x, fmaf(qq.y, kk.y,
                      fmaf(qq.z, kk.z, fmaf(qq.w, kk.w, acc))));
            }
            s_QXk[h][n] = acc * QSCALE;
        } else if (tid < 280){
            int t = tid - 256;
            int h = t/3, a = t%3;
            float acc = 0.0f;
            #pragma unroll
            for (int j = 0; j < 16; j++) acc = fmaf(s_q[h*16+j], g_Mk[a*DD + h*16 + j], acc);
            s_qMk[h][a] = acc * QSCALE;
        } else if (tid < 288){
            int h = tid - 280;
            float acc = 0.0f;
            #pragma unroll
            for (int j = 0; j < 16; j++) acc = fmaf(s_q[h*16+j], g_uk[h*16+j], acc);
            s_quk[h] = acc * QSCALE;
        } else if (tid < 296){
            int h = tid - 288;
            float acc = 0.0f;
            #pragma unroll
            for (int j = 0; j < 16; j++) acc = fmaf(s_q[h*16+j], g_ck[h*16+j], acc);
            s_qck[h] = acc * QSCALE;
        }
        __syncthreads();
    }

    // scores + LN stats: one key per thread (deltas already in smem)
    if (tid < LL){
        int l = tid;
        int n = l & 31;
        float d0 = s_dc0[l], d1 = s_dc1[l], d2 = s_dc2[l];
        float mu = s_mxb[n] + (d0*g_rs[0] + d1*g_rs[1] + d2*g_rs[2]) * (1.0f/128.0f);
        float ss = s_ssxb[n]
                 + 2.0f*(d0*s_XW[n][0] + d1*s_XW[n][1] + d2*s_XW[n][2])
                 + d0*(g_G[0]*d0 + g_G[1]*d1 + g_G[2]*d2)
                 + d1*(g_G[3]*d0 + g_G[4]*d1 + g_G[5]*d2)
                 + d2*(g_G[6]*d0 + g_G[7]*d1 + g_G[8]*d2);
        float var = ss*(1.0f/128.0f) - mu*mu;
        float rstd = rsqrtf(var + 1e-5f);
        s_rstd[l] = rstd;
        float rm = rstd*mu;
        bool msk = (mk[n] == 0);
        #pragma unroll
        for (int h = 0; h < 8; h++){
            float s = rstd*(s_QXk[h][n] + d0*s_qMk[h][0] + d1*s_qMk[h][1] + d2*s_qMk[h][2])
                    - rm*s_quk[h] + s_qck[h];
            s_buf[h*LL + l] = msk ? -1e9f : s;
        }
    }
    __syncthreads();

    // softmax (exp2 domain): 4 warps per head; warp q owns keys c = q (mod 4)
    // loops manually unrolled (6 + conditional tail) for load batching
    {
        int h = w & 7, q = w >> 3;
        int start = q*32 + lane;
        float* sch = s_buf + h*LL;
        bool has7 = (start + 6*128) < LL;

        float v0 = sch[start],        v1 = sch[start+128];
        float v2 = sch[start+2*128],  v3 = sch[start+3*128];
        float v4 = sch[start+4*128],  v5 = sch[start+5*128];
        float v6 = has7 ? sch[start+6*128] : -3.4e38f;
        float m = fmaxf(fmaxf(fmaxf(v0,v1), fmaxf(v2,v3)), fmaxf(fmaxf(v4,v5), v6));
        #pragma unroll
        for (int o = 16; o; o >>= 1) m = fmaxf(m, __shfl_xor_sync(0xffffffffu, m, o));

        float e0 = exp2f(v0-m), e1 = exp2f(v1-m), e2 = exp2f(v2-m);
        float e3 = exp2f(v3-m), e4 = exp2f(v4-m), e5 = exp2f(v5-m);
        float e6 = has7 ? exp2f(v6-m) : 0.0f;
        sch[start]       = e0; sch[start+128]   = e1;
        sch[start+2*128] = e2; sch[start+3*128] = e3;
        sch[start+4*128] = e4; sch[start+5*128] = e5;
        if (has7) sch[start+6*128] = e6;
        float sum = ((e0+e1)+(e2+e3)) + ((e4+e5)+e6);
        #pragma unroll
        for (int o = 16; o; o >>= 1) sum += __shfl_xor_sync(0xffffffffu, sum, o);
        if (lane == 0){ s_sm4[q][h][0] = m; s_sm4[q][h][1] = sum; }
    }
    __syncthreads();

    // V aggregates: warp (q,h) covers c = q (mod 4); one constant merge scale.
    // Gp analytic. Unrolled 6 + conditional tail.
    {
        int n = lane;
        int h = w & 7, q = w >> 3;
        float m0 = s_sm4[0][h][0], m1 = s_sm4[1][h][0];
        float m2 = s_sm4[2][h][0], m3 = s_sm4[3][h][0];
        float M = fmaxf(fmaxf(m0, m1), fmaxf(m2, m3));
        float e0 = exp2f(m0-M), e1 = exp2f(m1-M), e2 = exp2f(m2-M), e3 = exp2f(m3-M);
        float Sinv = 1.0f/(s_sm4[0][h][1]*e0 + s_sm4[1][h][1]*e1
                         + s_sm4[2][h][1]*e2 + s_sm4[3][h][1]*e3);
        float scl = ((q==0) ? e0 : ((q==1) ? e1 : ((q==2) ? e2 : e3))) * Sinv;

        const float* sch = s_buf + h*LL;
        float A = 0.f, B0 = 0.f, B1 = 0.f, B2 = 0.f;
        #pragma unroll
        for (int t = 0; t < 6; t++){
            int l = (q + t*4)*32 + n;
            float wr = sch[l] * s_rstd[l];
            A += wr;
            B0 = fmaf(wr, s_dc0[l], B0);
            B1 = fmaf(wr, s_dc1[l], B1);
            B2 = fmaf(wr, s_dc2[l], B2);
        }
        if (q < 3){
            int l = (q + 24)*32 + n;
            float wr = sch[l] * s_rstd[l];
            A += wr;
            B0 = fmaf(wr, s_dc0[l], B0);
            B1 = fmaf(wr, s_dc1[l], B1);
            B2 = fmaf(wr, s_dc2[l], B2);
        }
        float Gp = -s_mxb[n]*A
                 - (B0*g_rs[0] + B1*g_rs[1] + B2*g_rs[2]) * (1.0f/128.0f);
        A *= scl; B0 *= scl; B1 *= scl; B2 *= scl; Gp *= scl;
        s_Ap[q][h][n] = A;
        B0 = warpSum(B0); B1 = warpSum(B1); B2 = warpSum(B2); Gp = warpSum(Gp);
        if (n == 0){
            s_Bp[q][h][0]=B0; s_Bp[q][h][1]=B1; s_Bp[q][h][2]=B2; s_Gp4[q][h]=Gp;
        }
    }
    __syncthreads();
    if (tid < 256){
        int h = tid >> 5, n = tid & 31;
        s_A[h][n] = s_Ap[0][h][n] + s_Ap[1][h][n] + s_Ap[2][h][n] + s_Ap[3][h][n];
    } else if (tid < 280){
        int t = tid - 256;
        int h = t/3, a = t%3;
        s_B[h][a] = s_Bp[0][h][a] + s_Bp[1][h][a] + s_Bp[2][h][a] + s_Bp[3][h][a];
    } else if (tid < 288){
        int h = tid - 280;
        s_G8[h] = s_Gp4[0][h] + s_Gp4[1][h] + s_Gp4[2][h] + s_Gp4[3][h];
    }
    __syncthreads();

    // atts: n-split 8 (4-iter chains), coalesced Xv reads
    {
        float* pa = s_buf;             // 1024 partials
        {
            int d = tid & 127, nh = tid >> 7;
            int h = d >> 4;
            float acc;
            if (nh == 0){
                acc = g_cv[d] + s_G8[h]*g_uv[d]
                    + s_B[h][0]*g_Mv[d] + s_B[h][1]*g_Mv[DD+d] + s_B[h][2]*g_Mv[2*DD+d];
            } else acc = 0.0f;
            const float* Xvb = g_Xv + b*32*DD;
            int n0 = nh*4;
            #pragma unroll
            for (int n = 0; n < 4; n++) acc = fmaf(s_A[h][n0+n], Xvb[(n0+n)*DD + d], acc);
            pa[nh*128 + d] = acc;
        }
        __syncthreads();
        if (tid < 128)
            s_atts[tid] = pa[tid] + pa[128+tid] + pa[256+tid] + pa[384+tid]
                        + pa[512+tid] + pa[640+tid] + pa[768+tid] + pa[896+tid];
        __syncthreads();

        // Wo: 32 col-quads x 32 k-splits (4 k each), float4, coalesced
        float* red = s_buf;            // 4096 partials
        {
            int cg = tid & 31, ks = tid >> 5;
            int k0 = ks*4, j4 = cg*4;
            const float* Wb = Wo + k0*DD + j4;
            float a0=0.f, a1=0.f, a2=0.f, a3=0.f;
            #pragma unroll
            for (int kk = 0; kk < 4; kk++){
                float a = s_atts[k0+kk];
                float4 wv = *(const float4*)&Wb[kk*DD];
                a0 = fmaf(a, wv.x, a0); a1 = fmaf(a, wv.y, a1);
                a2 = fmaf(a, wv.z, a2); a3 = fmaf(a, wv.w, a3);
            }
            float4 o; o.x=a0; o.y=a1; o.z=a2; o.w=a3;
            *(float4*)&red[ks*128 + j4] = o;
        }
        __syncthreads();

        // y = xb + bo + sum(32 partials); warp stats; then warp0 LN2+hn2
        if (tid < 128){
            float y = s_xb[tid] + bo[tid];
            #pragma unroll
            for (int t = 0; t < 32; t++) y += red[t*128 + tid];
            s_yrow[tid] = y;
            float s = warpSum(y), s2 = warpSum(y*y);
            if (lane == 0){ rsm[w][0] = s; rsm[w][1] = s2; }
        }
        __syncthreads();
        if (tid < 32){
            float s  = rsm[0][0]+rsm[1][0]+rsm[2][0]+rsm[3][0];
            float s2 = rsm[0][1]+rsm[1][1]+rsm[2][1]+rsm[3][1];
            float m = s * (1.0f/128.0f);
            float rstd = rsqrtf(s2*(1.0f/128.0f) - m*m + 1e-5f);
            #pragma unroll
            for (int r = 0; r < 4; r++){
                int d = r*32 + lane;
                s_hn2[d] = (s_yrow[d] - m)*rstd*g2[d] + b2[d];
            }
        }
        __syncthreads();
    }

    // ===================== PHASE 3: FFN (float4, coalesced) ===================
    {
        float* zp = s_buf;             // 8*512 = 4096 partials
        float* zs = s_buf + 4096;      // 512

        // stage 1: 128 col-quads x 8 k-octants, full unroll
        {
            int cg = tid & 127, ko = tid >> 7;
            int k0 = ko*16, j4 = cg*4;
            const float* Wb = W1 + k0*DFF + j4;
            float a0=0.f, a1=0.f, a2=0.f, a3=0.f;
            #pragma unroll
            for (int kk = 0; kk < 16; kk++){
                float a = s_hn2[k0+kk];
                float4 wv = *(const float4*)&Wb[kk*DFF];
                a0 = fmaf(a, wv.x, a0); a1 = fmaf(a, wv.y, a1);
                a2 = fmaf(a, wv.z, a2); a3 = fmaf(a, wv.w, a3);
            }
            float4 o; o.x=a0; o.y=a1; o.z=a2; o.w=a3;
            *(float4*)&zp[ko*512 + j4] = o;
        }
        __syncthreads();
        if (tid < 512){
            float v = zp[tid] + zp[512+tid] + zp[1024+tid] + zp[1536+tid]
                    + zp[2048+tid] + zp[2560+tid] + zp[3072+tid] + zp[3584+tid];
            zs[tid] = fmaxf(v + bf1[tid], 0.0f);
        }
        __syncthreads();

        // stage 2: 32 col-quads x 32 k-splits (16 k each), full unroll
        float* red = s_buf;            // 4096 (zp region reused; zs disjoint)
        {
            int cg = tid & 31, ks = tid >> 5;
            int k0 = ks*16, j4 = cg*4;
            const float* Wb = W2 + k0*DD + j4;
            float a0=0.f, a1=0.f, a2=0.f, a3=0.f;
            #pragma unroll
            for (int kk = 0; kk < 16; kk++){
                float a = zs[k0+kk];
                float4 wv = *(const float4*)&Wb[kk*DD];
                a0 = fmaf(a, wv.x, a0); a1 = fmaf(a, wv.y, a1);
                a2 = fmaf(a, wv.z, a2); a3 = fmaf(a, wv.w, a3);
            }
            float4 o; o.x=a0; o.y=a1; o.z=a2; o.w=a3;
            *(float4*)&red[ks*128 + j4] = o;
        }
        __syncthreads();

        // final: 128 threads sum all 32 partials straight into out
        if (tid < 128){
            float v = s_yrow[tid] + bf2[tid];
            #pragma unroll
            for (int t = 0; t < 32; t++) v += red[t*128 + tid];
            out[bid*DD + tid] = v;
        }
    }
}

// ---------------- launch ------------------------------------------------------
extern "C" void kernel_launch(void* const* d_in, const int* in_sizes, int n_in,
                              void* d_out, int out_size)
{
    const float* x      = (const float*)d_in[0];
    const int*   mask   = (const int*)  d_in[1];
    const float* coords = (const float*)d_in[2];
    const float* Wp = (const float*)d_in[3],  *bp  = (const float*)d_in[4];
    const float* Wq = (const float*)d_in[5],  *bq  = (const float*)d_in[6];
    const float* Wk = (const float*)d_in[7],  *bk  = (const float*)d_in[8];
    const float* Wv = (const float*)d_in[9],  *bv  = (const float*)d_in[10];
    const float* Wo = (const float*)d_in[11], *bo  = (const float*)d_in[12];
    const float* g1 = (const float*)d_in[13], *b1  = (const float*)d_in[14];
    const float* g2 = (const float*)d_in[15], *b2  = (const float*)d_in[16];
    const float* W1 = (const float*)d_in[17], *bf1 = (const float*)d_in[18];
    const float* W2 = (const float*)d_in[19], *bf2 = (const float*)d_in[20];
    float* out = (float*)d_out;

    k_fused<<<GRID, TPB>>>(x, mask, coords, Wp, bp, Wq, bq, Wk, bk, Wv, bv,
                           Wo, bo, g1, b1, g2, b2, W1, bf1, W2, bf2, out);
}